// round 3
// baseline (speedup 1.0000x reference)
#include <cuda_runtime.h>
#include <math.h>

#define BB  512          // batch
#define TT  55           // timesteps
#define CC  512          // input width
#define DD  512          // hidden
#define KK  64           // key size
#define LL  3            // layers
#define OO  512          // output
#define BT  (BB*TT)      // 28160
#define BD  (BB*DD)      // 262144
#define G4  2048         // 4*D

// ---------------- device scratch (static globals; no allocation) ----------------
__device__ float g_Grx[(size_t)LL*BT*KK];     // precomputed X @ wr_w[l] (x-rows part)
__device__ float g_h[2*LL*BD];                // ping-pong h state
__device__ float g_c[LL*BD];
__device__ float g_d[LL*BB*KK];
__device__ float g_dd[BD];                    // tanh(d_new @ wd) for current layer
__device__ float g_part[4*(size_t)BB*G4];     // gate GEMM K-split partials (z<=4)
__device__ float g_ppart[3*(size_t)BB*OO];    // proj GEMM partials (z=3)

struct Seg  { const float* A; long long lda; const float* Bw; long long ldb; };
struct Segs { Seg s[4]; };

__device__ __forceinline__ float sigm(float x) { return 1.0f/(1.0f+expf(-x)); }

// ---------------- generic segmented SGEMM ----------------
// Each block computes a BMxBN tile of (A_z @ B_z) where z = blockIdx.z selects the
// segment. K is fixed at 512 per segment. Output written to out + z*zstride.
// All our GEMM shapes have K=512 segments; M % 64 == 0; N guarded.
template<int BN, int TM, int TN>
__global__ void sgemm_seg(Segs segs, const float* __restrict__ bias,
                          float* __restrict__ out, long long ldc, long long zstride,
                          int M, int N)
{
    constexpr int BM = 64, BK = 16;
    constexpr int TX = BN / TN;           // 16
    // TY = BM/TM = 16  -> 256 threads
    __shared__ __align__(16) float a_s[BK][BM];
    __shared__ __align__(16) float b_s[BK][BN];

    const int tid  = threadIdx.x;
    const int tx   = tid % TX;
    const int ty   = tid / TX;
    const int row0 = blockIdx.y * BM;
    const int col0 = blockIdx.x * BN;
    const Seg sg   = segs.s[blockIdx.z];

    float acc[TM][TN];
#pragma unroll
    for (int i = 0; i < TM; i++)
#pragma unroll
        for (int j = 0; j < TN; j++) acc[i][j] = 0.0f;

    const int ar = tid >> 2;          // 0..63  row within A tile
    const int ak = (tid & 3) << 2;    // 0,4,8,12

    for (int k0 = 0; k0 < 512; k0 += BK) {
        // load A tile [BM x BK], stored transposed a_s[k][m]
        {
            float4 av = *(const float4*)(sg.A + (long long)(row0 + ar)*sg.lda + k0 + ak);
            a_s[ak+0][ar] = av.x; a_s[ak+1][ar] = av.y;
            a_s[ak+2][ar] = av.z; a_s[ak+3][ar] = av.w;
        }
        // load B tile [BK x BN] (N-guarded)
#pragma unroll
        for (int i = 0; i < (BK*BN/4)/256; i++) {
            int e   = tid + i*256;
            int kk  = e / (BN/4);
            int n4  = (e % (BN/4)) * 4;
            int col = col0 + n4;
            float4 bv = make_float4(0.f,0.f,0.f,0.f);
            if (col < N) bv = *(const float4*)(sg.Bw + (long long)(k0+kk)*sg.ldb + col);
            *(float4*)&b_s[kk][n4] = bv;
        }
        __syncthreads();
#pragma unroll
        for (int kk = 0; kk < BK; kk++) {
            float af[TM], bf[TN];
            *(float4*)&af[0] = *(const float4*)&a_s[kk][ty*TM];   // TM==4
#pragma unroll
            for (int j = 0; j < TN; j += 4)
                *(float4*)&bf[j] = *(const float4*)&b_s[kk][tx*TN + j];
#pragma unroll
            for (int i = 0; i < TM; i++)
#pragma unroll
                for (int j = 0; j < TN; j++)
                    acc[i][j] = fmaf(af[i], bf[j], acc[i][j]);
        }
        __syncthreads();
    }

    float* o = out + (long long)blockIdx.z * zstride;
#pragma unroll
    for (int i = 0; i < TM; i++) {
        int r = row0 + ty*TM + i;
#pragma unroll
        for (int j = 0; j < TN; j++) {
            int cn = col0 + tx*TN + j;
            if (cn < N) {
                float v = acc[i][j];
                if (bias) v += bias[cn];
                o[(long long)r*ldc + cn] = v;
            }
        }
    }
}

// ---------------- key-gate kernel (per layer, per step) ----------------
// gr = Grx + sum_{j<l} hnew_j @ wr_l[rows C+jD..] + (1/3) sum_{j<l} hprev_j @ wl_j
// r = sigmoid(gr); d = r*d;  dd = tanh(d @ wd)
__global__ void k1_kernel(int l, int t,
                          const float* __restrict__ hp, const float* __restrict__ hn,
                          const float* __restrict__ grx,
                          const float* __restrict__ wr_l,
                          const float* __restrict__ wl0, const float* __restrict__ wl1,
                          const float* __restrict__ wd,
                          float* __restrict__ dstate, float* __restrict__ dd)
{
    __shared__ float dn_s[4][KK];
    const int tid = threadIdx.x;        // 256
    const int r   = tid >> 6;           // 0..3 (batch row within block)
    const int kk  = tid & 63;
    const int b   = blockIdx.x*4 + r;

    float acc = grx[((long long)b*TT + t)*KK + kk];
    for (int j = 0; j < l; j++) {
        const float* hnj = hn + (size_t)j*BD + (size_t)b*DD;
        const float* hpj = hp + (size_t)j*BD + (size_t)b*DD;
        const float* wrp = wr_l + (size_t)(CC + j*DD)*KK + kk;
        const float* wlp = (j == 0 ? wl0 : wl1) + kk;
        float a2 = 0.0f;
#pragma unroll 8
        for (int m = 0; m < DD; m++) {
            acc = fmaf(hnj[m], wrp[(size_t)m*KK], acc);
            a2  = fmaf(hpj[m], wlp[(size_t)m*KK], a2);
        }
        acc += a2 * (1.0f/3.0f);
    }
    float rr = sigm(acc);
    float dn = rr * dstate[b*KK + kk];
    dstate[b*KK + kk] = dn;
    dn_s[r][kk] = dn;
    __syncthreads();

    // dd = tanh(d_new @ wd), 4 rows x 512 cols per block
    for (int e = tid; e < 4*DD; e += 256) {
        int r2 = e >> 9;
        int n  = e & 511;
        int bb = blockIdx.x*4 + r2;
        float s = 0.0f;
#pragma unroll
        for (int q = 0; q < KK; q++)
            s = fmaf(dn_s[r2][q], wd[(size_t)q*DD + n], s);
        dd[(size_t)bb*DD + n] = tanhf(s);
    }
}

// ---------------- LSTM elementwise update (also reduces gate K-split partials) ----------------
__global__ void lstm_update(int nparts,
                            const float* __restrict__ wxb, const float* __restrict__ whb,
                            const float* __restrict__ part, const float* __restrict__ dd,
                            float* __restrict__ c, float* __restrict__ h)
{
    const long long idx = (long long)blockIdx.x*256 + threadIdx.x;   // < B*D
    const int b = (int)(idx >> 9);
    const int n = (int)(idx & 511);
    const long long pbase = (long long)b*G4;

    float g0 = wxb[n]        + whb[n];
    float g1 = wxb[DD+n]     + whb[DD+n];
    float g2 = wxb[2*DD+n]   + whb[2*DD+n];
    float g3 = wxb[3*DD+n]   + whb[3*DD+n];
    for (int z = 0; z < nparts; z++) {
        const float* pp = part + (long long)z*BB*G4 + pbase;
        g0 += pp[n]; g1 += pp[DD+n]; g2 += pp[2*DD+n]; g3 += pp[3*DD+n];
    }
    float f  = sigm(g0);
    float i  = sigm(g1);
    float o  = sigm(g2);
    float cb = tanhf(g3);
    float cv = f*c[idx] + i*cb + dd[idx];
    c[idx] = cv;
    h[idx] = o * tanhf(cv);
}

// ---------------- projection output (reduce partials + bias) ----------------
__global__ void projout(int t, const float* __restrict__ pb,
                        const float* __restrict__ pp, float* __restrict__ out)
{
    const long long idx = (long long)blockIdx.x*256 + threadIdx.x;   // < B*OUT
    const int b = (int)(idx >> 9);
    const int n = (int)(idx & 511);
    float v = pb[n] + pp[idx] + pp[(long long)BB*OO + idx] + pp[2ll*BB*OO + idx];
    out[(long long)b*TT*OO + (long long)t*OO + n] = v;
}

// ---------------- state init (runs every launch -> deterministic replays) ----------------
__global__ void init_kernel(float* __restrict__ h, float* __restrict__ c,
                            float* __restrict__ d, const float* __restrict__ keys)
{
    for (long long idx = (long long)blockIdx.x*256 + threadIdx.x;
         idx < 2ll*LL*BD; idx += (long long)gridDim.x*256) {
        h[idx] = 0.0f;
        if (idx < (long long)LL*BD)    c[idx] = 0.0f;
        if (idx < (long long)LL*BB*KK) d[idx] = keys[idx % (BB*KK)];
    }
}

// ---------------- host orchestration ----------------
extern "C" void kernel_launch(void* const* d_in, const int* in_sizes, int n_in,
                              void* d_out, int out_size)
{
    const float* X    = (const float*)d_in[0];
    const float* keys = (const float*)d_in[1];

    const float *wx_w[LL], *wx_b[LL], *wh_w[LL], *wh_b[LL], *wr_w[LL], *wl_w[LL];
    if (in_sizes[4] == 512*2048) {
        // dict order: per-layer interleaved (wx_w, wx_b, wh_w, wh_b, wr_w, wl_w)
        for (int l = 0; l < LL; l++) {
            int base = 2 + 6*l;
            wx_w[l] = (const float*)d_in[base+0];
            wx_b[l] = (const float*)d_in[base+1];
            wh_w[l] = (const float*)d_in[base+2];
            wh_b[l] = (const float*)d_in[base+3];
            wr_w[l] = (const float*)d_in[base+4];
            wl_w[l] = (const float*)d_in[base+5];
        }
    } else {
        // signature order: wx0..2 (w,b), wh0..2 (w,b), wr0..2, wl0..2
        for (int l = 0; l < LL; l++) {
            wx_w[l] = (const float*)d_in[2 + 2*l];
            wx_b[l] = (const float*)d_in[3 + 2*l];
            wh_w[l] = (const float*)d_in[8 + 2*l];
            wh_b[l] = (const float*)d_in[9 + 2*l];
            wr_w[l] = (const float*)d_in[14 + l];
            wl_w[l] = (const float*)d_in[17 + l];
        }
    }
    const float* wd     = (const float*)d_in[20];
    const float* proj_w = (const float*)d_in[21];
    const float* proj_b = (const float*)d_in[22];
    float* out = (float*)d_out;

    float *p_Grx, *p_h, *p_c, *p_d, *p_dd, *p_part, *p_ppart;
    cudaGetSymbolAddress((void**)&p_Grx,   g_Grx);
    cudaGetSymbolAddress((void**)&p_h,     g_h);
    cudaGetSymbolAddress((void**)&p_c,     g_c);
    cudaGetSymbolAddress((void**)&p_d,     g_d);
    cudaGetSymbolAddress((void**)&p_dd,    g_dd);
    cudaGetSymbolAddress((void**)&p_part,  g_part);
    cudaGetSymbolAddress((void**)&p_ppart, g_ppart);

    // reset recurrent state (every call; graph replays stay deterministic)
    init_kernel<<<6144, 256>>>(p_h, p_c, p_d, keys);

    // precompute Grx_l = X @ wr_w[l][:C]  for all (b,t) rows  (M=BT, N=64)
    for (int l = 0; l < LL; l++) {
        Segs sg{};
        sg.s[0] = { X, (long long)CC, wr_w[l], (long long)KK };
        dim3 g(1, BT/64, 1);
        sgemm_seg<128,4,8><<<g, 256>>>(sg, nullptr,
                                       p_Grx + (long long)l*BT*KK,
                                       KK, 0, BT, KK);
    }

    for (int t = 0; t < TT; t++) {
        int par = t & 1;
        float* hp = p_h + (long long)par     * LL * BD;   // previous-step h
        float* hn = p_h + (long long)(1-par) * LL * BD;   // this-step h

        for (int l = 0; l < LL; l++) {
            // key gate: gr -> r -> d update -> dd = tanh(d @ wd)
            k1_kernel<<<BB/4, 256>>>(l, t, hp, hn,
                                     p_Grx + (long long)l*BT*KK,
                                     wr_w[l], wl_w[0], wl_w[1], wd,
                                     p_d + (long long)l*BB*KK, p_dd);

            // gate GEMM, K split across blockIdx.z segments (x, h_prev_l, h_new_j...)
            Segs sg{};
            sg.s[0] = { X + (long long)t*CC, (long long)TT*CC, wx_w[l], (long long)G4 };
            sg.s[1] = { hp + (long long)l*BD, (long long)DD,   wh_w[l], (long long)G4 };
            for (int j = 0; j < l; j++)
                sg.s[2+j] = { hn + (long long)j*BD, (long long)DD,
                              wx_w[l] + (long long)(CC + j*DD)*G4, (long long)G4 };
            dim3 gg(G4/128, BB/64, l+2);
            sgemm_seg<128,4,8><<<gg, 256>>>(sg, nullptr, p_part,
                                            G4, (long long)BB*G4, BB, G4);

            // elementwise LSTM update (reduces the z partials + biases)
            lstm_update<<<BD/256, 256>>>(l+2, wx_b[l], wh_b[l], p_part, p_dd,
                                         p_c + (long long)l*BD,
                                         hn + (long long)l*BD);
        }

        // projection: out_t = concat(h) @ proj_w + proj_b   (K split z=3)
        Segs ps{};
        for (int l = 0; l < LL; l++)
            ps.s[l] = { hn + (long long)l*BD, (long long)DD,
                        proj_w + (long long)l*DD*OO, (long long)OO };
        dim3 pg(OO/64, BB/64, 3);
        sgemm_seg<64,4,4><<<pg, 256>>>(ps, nullptr, p_ppart,
                                       OO, (long long)BB*OO, BB, OO);
        projout<<<BB*OO/256, 256>>>(t, proj_b, p_ppart, out);
    }
}

// round 4
// speedup vs baseline: 1.8967x; 1.8967x over previous
#include <cuda_runtime.h>
#include <math.h>

#define BB  512          // batch
#define TT  55           // timesteps
#define CC  512          // input width
#define DD  512          // hidden
#define KK  64           // key size
#define LL  3            // layers
#define OO  512          // output
#define BT  (BB*TT)      // 28160
#define BD  (BB*DD)      // 262144
#define G4  2048         // 4*D

// ---------------- device scratch (static globals; no allocation) ----------------
__device__ float g_gx[(size_t)LL*BT*G4];      // X @ wx_w[l][:C]  for all (b,t)   (692 MB)
__device__ float g_Grx[(size_t)LL*BT*KK];     // X @ wr_w[l][:C]
__device__ float g_d0all[(size_t)BT*KK];      // layer-0 d state for all t (x-only scan)
__device__ float g_dd0[(size_t)BT*DD];        // d0all @ wd (raw; tanh applied in update)
__device__ float g_h[2*LL*BD];                // ping-pong h state
__device__ float g_c[LL*BD];
__device__ float g_d[LL*BB*KK];
__device__ float g_dd[BD];                    // tanh(d_new @ wd) for current layer (l>=1)
__device__ float g_part[6*(size_t)BB*G4];     // gate GEMM K-split partials (z<=6)
__device__ float g_ppart[6*(size_t)BB*OO];    // proj GEMM partials (z=6)

struct Seg  { const float* A; long long lda; const float* Bw; long long ldb; int K; };
struct Segs { Seg s[6]; };

__device__ __forceinline__ float sigm(float x) { return 1.0f/(1.0f+expf(-x)); }

// ---- packed f32x2 helpers (FFMA2: ptxas won't emit from C++, PTX only) ----
__device__ __forceinline__ void fma2(unsigned long long &d, unsigned long long a, unsigned long long b){
    asm("fma.rn.f32x2 %0, %1, %2, %0;" : "+l"(d) : "l"(a), "l"(b));
}
__device__ __forceinline__ unsigned long long bcast2(float x){
    unsigned long long r; asm("mov.b64 %0, {%1, %1};" : "=l"(r) : "f"(x)); return r;
}
__device__ __forceinline__ unsigned long long pk2(float lo, float hi){
    unsigned long long r; asm("mov.b64 %0, {%1, %2};" : "=l"(r) : "f"(lo), "f"(hi)); return r;
}
__device__ __forceinline__ float2 unpk(unsigned long long v){
    float2 f; asm("mov.b64 {%0, %1}, %2;" : "=f"(f.x), "=f"(f.y) : "l"(v)); return f;
}

// ---------------- segmented SGEMM with packed f32x2 FMA ----------------
// BM=64 fixed, BK=16. Each block: BMxBN tile of A_z @ B_z (z = blockIdx.z).
// Requires M % 64 == 0, N % BN == 0, K % 16 == 0. Out += z*zstride.
template<int BN, int TM, int TN>
__global__ void __launch_bounds__((BN/TN)*(64/TM))
gemm2(Segs segs, float* __restrict__ out, long long ldc, long long zstride)
{
    constexpr int BM = 64, BK = 16;
    constexpr int TX = BN/TN, TY = BM/TM, NT = TX*TY;
    __shared__ __align__(16) float a_s[BK][BM];
    __shared__ __align__(16) float b_s[BK][BN];

    const int tid  = threadIdx.x;
    const int tx   = tid % TX;
    const int ty   = tid / TX;
    const int row0 = blockIdx.y * BM;
    const int col0 = blockIdx.x * BN;
    const Seg sg   = segs.s[blockIdx.z];

    unsigned long long acc[TM][TN/2];
#pragma unroll
    for (int i = 0; i < TM; i++)
#pragma unroll
        for (int j = 0; j < TN/2; j++) acc[i][j] = 0ull;   // bits(0,0) == (0.f,0.f)

    for (int k0 = 0; k0 < sg.K; k0 += BK) {
        // A tile [BM x BK] -> a_s transposed a_s[k][m]
#pragma unroll
        for (int e = tid; e < BM*BK/4; e += NT) {
            int r  = e >> 2;            // 0..63
            int kq = (e & 3) << 2;      // 0,4,8,12
            float4 v = *(const float4*)(sg.A + (long long)(row0 + r)*sg.lda + k0 + kq);
            a_s[kq+0][r] = v.x; a_s[kq+1][r] = v.y;
            a_s[kq+2][r] = v.z; a_s[kq+3][r] = v.w;
        }
        // B tile [BK x BN]
#pragma unroll
        for (int e = tid; e < BK*BN/4; e += NT) {
            int kk = e / (BN/4);
            int n4 = (e % (BN/4)) * 4;
            *(float4*)&b_s[kk][n4] =
                *(const float4*)(sg.Bw + (long long)(k0+kk)*sg.ldb + col0 + n4);
        }
        __syncthreads();
#pragma unroll
        for (int kk = 0; kk < BK; kk++) {
            float af[TM], bf[TN];
#pragma unroll
            for (int i = 0; i < TM; i += 4)
                *(float4*)&af[i] = *(const float4*)&a_s[kk][ty*TM + i];
#pragma unroll
            for (int j = 0; j < TN; j += 4)
                *(float4*)&bf[j] = *(const float4*)&b_s[kk][tx*TN + j];
            unsigned long long bb[TN/2];
#pragma unroll
            for (int j = 0; j < TN/2; j++) bb[j] = pk2(bf[2*j], bf[2*j+1]);
#pragma unroll
            for (int i = 0; i < TM; i++) {
                unsigned long long aa = bcast2(af[i]);
#pragma unroll
                for (int j = 0; j < TN/2; j++) fma2(acc[i][j], aa, bb[j]);
            }
        }
        __syncthreads();
    }

    float* o = out + (long long)blockIdx.z * zstride;
#pragma unroll
    for (int i = 0; i < TM; i++) {
        long long r = row0 + ty*TM + i;
#pragma unroll
        for (int j = 0; j < TN/2; j++) {
            float2 v = unpk(acc[i][j]);
            *(float2*)&o[r*ldc + col0 + tx*TN + 2*j] = v;
        }
    }
}

// ---------------- key-gate kernel (layers 1,2 only; per step) ----------------
// gr = Grx + sum_{j<l} hnew_j @ wr_l[rows C+jD..] + (1/3) sum_{j<l} hprev_j @ wl_j
// r = sigmoid(gr); d = r*d;  dd = tanh(d @ wd)
__global__ void k1_kernel(int l, int t,
                          const float* __restrict__ hp, const float* __restrict__ hn,
                          const float* __restrict__ grx,
                          const float* __restrict__ wr_l,
                          const float* __restrict__ wl0, const float* __restrict__ wl1,
                          const float* __restrict__ wd,
                          float* __restrict__ dstate, float* __restrict__ dd)
{
    __shared__ float dn_s[4][KK];
    const int tid = threadIdx.x;        // 256
    const int r   = tid >> 6;           // 0..3 (batch row within block)
    const int kk  = tid & 63;
    const int b   = blockIdx.x*4 + r;

    float acc = grx[((long long)b*TT + t)*KK + kk];
    for (int j = 0; j < l; j++) {
        const float* hnj = hn + (size_t)j*BD + (size_t)b*DD;
        const float* hpj = hp + (size_t)j*BD + (size_t)b*DD;
        const float* wrp = wr_l + (size_t)(CC + j*DD)*KK + kk;
        const float* wlp = (j == 0 ? wl0 : wl1) + kk;
        float s0=0.f,s1=0.f,s2=0.f,s3=0.f;
        float u0=0.f,u1=0.f,u2=0.f,u3=0.f;
#pragma unroll 4
        for (int m = 0; m < DD; m += 4) {
            s0 = fmaf(hnj[m+0], wrp[(size_t)(m+0)*KK], s0);
            s1 = fmaf(hnj[m+1], wrp[(size_t)(m+1)*KK], s1);
            s2 = fmaf(hnj[m+2], wrp[(size_t)(m+2)*KK], s2);
            s3 = fmaf(hnj[m+3], wrp[(size_t)(m+3)*KK], s3);
            u0 = fmaf(hpj[m+0], wlp[(size_t)(m+0)*KK], u0);
            u1 = fmaf(hpj[m+1], wlp[(size_t)(m+1)*KK], u1);
            u2 = fmaf(hpj[m+2], wlp[(size_t)(m+2)*KK], u2);
            u3 = fmaf(hpj[m+3], wlp[(size_t)(m+3)*KK], u3);
        }
        acc += (s0+s1)+(s2+s3) + ((u0+u1)+(u2+u3)) * (1.0f/3.0f);
    }
    float rr = sigm(acc);
    float dn = rr * dstate[b*KK + kk];
    dstate[b*KK + kk] = dn;
    dn_s[r][kk] = dn;
    __syncthreads();

    // dd = tanh(d_new @ wd), 4 rows x 512 cols per block
    for (int e = tid; e < 4*DD; e += 256) {
        int r2 = e >> 9;
        int n  = e & 511;
        int bb = blockIdx.x*4 + r2;
        float s = 0.0f;
#pragma unroll
        for (int q = 0; q < KK; q++)
            s = fmaf(dn_s[r2][q], wd[(size_t)q*DD + n], s);
        dd[(size_t)bb*DD + n] = tanhf(s);
    }
}

// ---------------- LSTM elementwise update (reduces K-split partials) ----------------
__global__ void lstm_update(int nparts, int t, int dd0mode,
                            const float* __restrict__ gx,
                            const float* __restrict__ wxb, const float* __restrict__ whb,
                            const float* __restrict__ part, const float* __restrict__ dd,
                            float* __restrict__ c, float* __restrict__ h)
{
    const long long idx = (long long)blockIdx.x*256 + threadIdx.x;   // < B*D
    const int b = (int)(idx >> 9);
    const int n = (int)(idx & 511);

    const float* gxr = gx + ((long long)b*TT + t)*G4;
    float g0 = gxr[n]        + wxb[n]        + whb[n];
    float g1 = gxr[DD+n]     + wxb[DD+n]     + whb[DD+n];
    float g2 = gxr[2*DD+n]   + wxb[2*DD+n]   + whb[2*DD+n];
    float g3 = gxr[3*DD+n]   + wxb[3*DD+n]   + whb[3*DD+n];
    const float* pp = part + (long long)b*G4;
    for (int z = 0; z < nparts; z++, pp += (long long)BB*G4) {
        g0 += pp[n]; g1 += pp[DD+n]; g2 += pp[2*DD+n]; g3 += pp[3*DD+n];
    }
    float f  = sigm(g0);
    float i  = sigm(g1);
    float o  = sigm(g2);
    float cb = tanhf(g3);
    float ddv = dd0mode ? tanhf(dd[((long long)b*TT + t)*DD + n]) : dd[idx];
    float cv = f*c[idx] + i*cb + ddv;
    c[idx] = cv;
    h[idx] = o * tanhf(cv);
}

// ---------------- layer-0 key scan: d0(t) = keys * prod sigm(Grx0) ----------------
__global__ void scan_d0(const float* __restrict__ grx0, const float* __restrict__ keys,
                        float* __restrict__ d0all)
{
    int i = blockIdx.x*256 + threadIdx.x;    // < B*K = 32768
    int b = i >> 6, kk = i & 63;
    float d = keys[i];
    for (int t = 0; t < TT; t++) {
        float g = grx0[((long long)b*TT + t)*KK + kk];
        d *= 1.0f/(1.0f + expf(-g));
        d0all[((long long)b*TT + t)*KK + kk] = d;
    }
}

// ---------------- projection output (reduce partials + bias) ----------------
__global__ void projout(int t, int nparts, const float* __restrict__ pb,
                        const float* __restrict__ pp, float* __restrict__ out)
{
    const long long idx = (long long)blockIdx.x*256 + threadIdx.x;   // < B*OUT
    const int b = (int)(idx >> 9);
    const int n = (int)(idx & 511);
    float v = pb[n];
    for (int z = 0; z < nparts; z++) v += pp[(long long)z*BB*OO + idx];
    out[((long long)b*TT + t)*OO + n] = v;
}

// ---------------- state init (runs every launch -> deterministic replays) ----------------
__global__ void init_kernel(float* __restrict__ h, float* __restrict__ c,
                            float* __restrict__ d, const float* __restrict__ keys)
{
    for (long long idx = (long long)blockIdx.x*256 + threadIdx.x;
         idx < 2ll*LL*BD; idx += (long long)gridDim.x*256) {
        h[idx] = 0.0f;
        if (idx < (long long)LL*BD)    c[idx] = 0.0f;
        if (idx < (long long)LL*BB*KK) d[idx] = keys[idx % (BB*KK)];
    }
}

// ---------------- host orchestration ----------------
extern "C" void kernel_launch(void* const* d_in, const int* in_sizes, int n_in,
                              void* d_out, int out_size)
{
    const float* X    = (const float*)d_in[0];
    const float* keys = (const float*)d_in[1];

    const float *wx_w[LL], *wx_b[LL], *wh_w[LL], *wh_b[LL], *wr_w[LL], *wl_w[LL];
    if (in_sizes[4] == 512*2048) {
        // dict order: per-layer interleaved (wx_w, wx_b, wh_w, wh_b, wr_w, wl_w)
        for (int l = 0; l < LL; l++) {
            int base = 2 + 6*l;
            wx_w[l] = (const float*)d_in[base+0];
            wx_b[l] = (const float*)d_in[base+1];
            wh_w[l] = (const float*)d_in[base+2];
            wh_b[l] = (const float*)d_in[base+3];
            wr_w[l] = (const float*)d_in[base+4];
            wl_w[l] = (const float*)d_in[base+5];
        }
    } else {
        // signature order
        for (int l = 0; l < LL; l++) {
            wx_w[l] = (const float*)d_in[2 + 2*l];
            wx_b[l] = (const float*)d_in[3 + 2*l];
            wh_w[l] = (const float*)d_in[8 + 2*l];
            wh_b[l] = (const float*)d_in[9 + 2*l];
            wr_w[l] = (const float*)d_in[14 + l];
            wl_w[l] = (const float*)d_in[17 + l];
        }
    }
    const float* wd     = (const float*)d_in[20];
    const float* proj_w = (const float*)d_in[21];
    const float* proj_b = (const float*)d_in[22];
    float* out = (float*)d_out;

    float *p_gx, *p_Grx, *p_d0all, *p_dd0, *p_h, *p_c, *p_d, *p_dd, *p_part, *p_ppart;
    cudaGetSymbolAddress((void**)&p_gx,    g_gx);
    cudaGetSymbolAddress((void**)&p_Grx,   g_Grx);
    cudaGetSymbolAddress((void**)&p_d0all, g_d0all);
    cudaGetSymbolAddress((void**)&p_dd0,   g_dd0);
    cudaGetSymbolAddress((void**)&p_h,     g_h);
    cudaGetSymbolAddress((void**)&p_c,     g_c);
    cudaGetSymbolAddress((void**)&p_d,     g_d);
    cudaGetSymbolAddress((void**)&p_dd,    g_dd);
    cudaGetSymbolAddress((void**)&p_part,  g_part);
    cudaGetSymbolAddress((void**)&p_ppart, g_ppart);

    // reset recurrent state
    init_kernel<<<6144, 256>>>(p_h, p_c, p_d, keys);

    // Grx_l = X @ wr_w[l][:C] for all (b,t)   (N=64, one launch, z=3)
    {
        Segs sg{};
        for (int l = 0; l < LL; l++)
            sg.s[l] = { X, (long long)CC, wr_w[l], (long long)KK, 512 };
        dim3 g(1, BT/64, 3);
        gemm2<64,4,8><<<g, 128>>>(sg, p_Grx, KK, (long long)BT*KK);
    }

    // layer-0 key path is x-only: scan d0 over t, then dd0 = d0all @ wd (raw)
    scan_d0<<<BB*KK/256, 256>>>(p_Grx, keys, p_d0all);
    {
        Segs sg{};
        sg.s[0] = { p_d0all, (long long)KK, wd, (long long)DD, KK };
        dim3 g(DD/128, BT/64, 1);
        gemm2<128,8,8><<<g, 128>>>(sg, p_dd0, DD, 0);
    }

    // Gx_l = X @ wx_w[l][:C] for all (b,t)   (the big parallel GEMM, z=3)
    {
        Segs sg{};
        for (int l = 0; l < LL; l++)
            sg.s[l] = { X, (long long)CC, wx_w[l], (long long)G4, 512 };
        dim3 g(G4/128, BT/64, 3);
        gemm2<128,8,8><<<g, 128>>>(sg, p_gx, G4, (long long)BT*G4);
    }

    for (int t = 0; t < TT; t++) {
        int par = t & 1;
        float* hp = p_h + (long long)par     * LL * BD;   // previous-step h
        float* hn = p_h + (long long)(1-par) * LL * BD;   // this-step h

        for (int l = 0; l < LL; l++) {
            if (l > 0) {
                // key gate for l>=1 (needs hn[j<l] and hp[j<l])
                k1_kernel<<<BB/4, 256>>>(l, t, hp, hn,
                                         p_Grx + (long long)l*BT*KK,
                                         wr_w[l], wl_w[0], wl_w[1], wd,
                                         p_d + (long long)l*BB*KK, p_dd);
            }

            // gate GEMM over h segments only, each K split into 2x256 chunks
            Segs sg{};
            int ns = 0;
            for (int kc = 0; kc < DD; kc += 256)
                sg.s[ns++] = { hp + (long long)l*BD + kc, (long long)DD,
                               wh_w[l] + (long long)kc*G4, (long long)G4, 256 };
            for (int j = 0; j < l; j++)
                for (int kc = 0; kc < DD; kc += 256)
                    sg.s[ns++] = { hn + (long long)j*BD + kc, (long long)DD,
                                   wx_w[l] + (long long)(CC + j*DD + kc)*G4,
                                   (long long)G4, 256 };
            dim3 gg(G4/128, BB/64, ns);
            gemm2<128,8,8><<<gg, 128>>>(sg, p_part, G4, (long long)BB*G4);

            // elementwise LSTM update (adds precomputed x-part + partials + biases)
            lstm_update<<<BD/256, 256>>>(ns, t, (l == 0) ? 1 : 0,
                                         p_gx + (long long)l*BT*G4,
                                         wx_b[l], wh_b[l], p_part,
                                         (l == 0) ? p_dd0 : p_dd,
                                         p_c + (long long)l*BD,
                                         hn + (long long)l*BD);
        }

        // projection: out_t = concat(h) @ proj_w + proj_b   (z = 6 K-chunks)
        {
            Segs ps{};
            int ns = 0;
            for (int l = 0; l < LL; l++)
                for (int kc = 0; kc < DD; kc += 256)
                    ps.s[ns++] = { hn + (long long)l*BD + kc, (long long)DD,
                                   proj_w + (long long)(l*DD + kc)*OO,
                                   (long long)OO, 256 };
            dim3 pg(OO/64, BB/64, ns);
            gemm2<64,4,8><<<pg, 128>>>(ps, p_ppart, OO, (long long)BB*OO);
            projout<<<BB*OO/256, 256>>>(t, ns, proj_b, p_ppart, out);
        }
    }
}